// round 16
// baseline (speedup 1.0000x reference)
#include <cuda_runtime.h>

typedef unsigned int U32;
typedef unsigned short U16;

static __device__ __forceinline__ float mish_f(float x){
    // mish(x) = x * ((1+e^x)^2 - 1) / ((1+e^x)^2 + 1), division via
    // bit-hack reciprocal + 2 Newton iterations (FMA pipe, no MUFU.RCP).
    float e  = __expf(fminf(x, 30.0f));
    float u  = 1.0f + e;
    float u2 = u * u;
    float d  = u2 + 1.0f;
    float r  = __int_as_float(0x7EF311C2 - __float_as_int(d));
    r = r * (2.0f - d * r);
    r = r * (2.0f - d * r);
    return x * (u2 - 1.0f) * r;
}

// g_AB: [pred(3)][half(2)][row(2048)][col(256)]  (P = x@W1_top, Q = x@W1_bot)
__device__ float g_AB[6 * 2048 * 256];
// g_W2h: W2 in fp16, fragment order: [pred(3)][nhalf(2)][chunk(4)][8192 halves]
__device__ U16 g_W2h[3 * 65536];

static __device__ __forceinline__ U32 pack_h2(float lo, float hi){
    U32 r;
    asm("cvt.rn.f16x2.f32 %0, %1, %2;" : "=r"(r) : "f"(hi), "f"(lo));
    return r;
}

// ---------------------------------------------------------------------------
// prep bodies
// ---------------------------------------------------------------------------
static __device__ void w2frag_body(int blk,
    const float* __restrict__ W2a, const float* __restrict__ W2b,
    const float* __restrict__ W2c)
{
    int idx = blk * 256 + threadIdx.x;          // 0 .. 196607
    int p = idx >> 16;
    int rem = idx & 65535;
    int k = rem >> 8, n = rem & 255;
    const float* W2 = (p == 0) ? W2a : (p == 1) ? W2b : W2c;
    float v = W2[k * 256 + n];
    U16 hv;
    asm("{ .reg .f16 t; cvt.rn.f16.f32 t, %1; mov.b16 %0, t; }" : "=h"(hv) : "f"(v));
    int c = k >> 6, kk = k & 63;
    int ks = kk >> 4, r = kk & 15;
    int hi = r >> 3, r8 = r & 7, tl = r8 >> 1, comp = r8 & 1;
    int nhalf = n >> 7, nl = n & 127;
    int nt = nl >> 3, np = nt >> 1, odd = nt & 1, g = nl & 7;
    int lane = g * 4 + tl;
    int halfidx = ((ks * 8 + np) * 32 + lane) * 8 + (odd * 2 + hi) * 2 + comp;
    g_W2h[((p * 2 + nhalf) * 4 + c) * 8192 + halfidx] = hv;
}

// ab: full-tile single-sync version. Xs[128 k][65 pad] + Ws[128 k][64].
static __device__ void ab_body(float* sh,
    const float* __restrict__ emb,
    const float* __restrict__ W1a, const float* __restrict__ W1b,
    const float* __restrict__ W1c,
    int bx, int by, int z)
{
    float (*Xs)[65] = (float(*)[65])sh;
    float (*Ws)[64] = (float(*)[64])(sh + 128*65);
    int p = z >> 1, half = z & 1;
    const float* W = (p == 0 ? W1a : (p == 1 ? W1b : W1c)) + half * 128 * 256;
    int row0 = by * 64;
    int col0 = bx * 64;
    int tid = threadIdx.x;
    int tr = tid >> 4, tc = tid & 15;

    #pragma unroll
    for (int it = 0; it < 32; it++){
        int idx = tid + it*256;       // idx = r*128 + k
        int r = idx >> 7, k = idx & 127;
        Xs[k][r] = emb[(row0 + r)*128 + k];
    }
    #pragma unroll
    for (int it = 0; it < 32; it++){
        int idx = tid + it*256;       // idx = k*64 + c
        int k = idx >> 6, c = idx & 63;
        Ws[k][c] = W[k*256 + col0 + c];
    }
    __syncthreads();

    float acc[4][4];
    #pragma unroll
    for (int r = 0; r < 4; r++)
        #pragma unroll
        for (int c = 0; c < 4; c++) acc[r][c] = 0.0f;

    #pragma unroll 4
    for (int k = 0; k < 128; k++){
        float a[4], bv[4];
        #pragma unroll
        for (int r = 0; r < 4; r++) a[r] = Xs[k][tr*4 + r];
        #pragma unroll
        for (int c = 0; c < 4; c++) bv[c] = Ws[k][tc*4 + c];
        #pragma unroll
        for (int r = 0; r < 4; r++)
            #pragma unroll
            for (int c = 0; c < 4; c++)
                acc[r][c] = fmaf(a[r], bv[c], acc[r][c]);
    }

    float* out = g_AB + (size_t)z * 2048 * 256;
    #pragma unroll
    for (int r = 0; r < 4; r++){
        float4 v = make_float4(acc[r][0], acc[r][1], acc[r][2], acc[r][3]);
        *(float4*)&out[(row0 + tr*4 + r)*256 + col0 + tc*4] = v;
    }
}

static __device__ void p0_body(float* sh,
    const float* __restrict__ emb,
    const float* __restrict__ W1, const float* __restrict__ b1,
    const float* __restrict__ W2, const float* __restrict__ b2,
    float* __restrict__ out, int blk)
{
    float (*buf)[33] = (float(*)[33])sh;                 // 128 x 33
    float (*wch)[128] = (float(*)[128])(sh + 4224);      // 16 x 128
    float* bias = sh + 4224 + 2048;
    int row0 = blk * 32;
    int tid = threadIdx.x;
    int tr = tid >> 5, tc = tid & 31;

    for (int idx = tid; idx < 32*128; idx += 256){
        int k = idx & 127, r = idx >> 7;
        buf[k][r] = emb[(row0 + r)*128 + k];
    }
    if (tid < 128) bias[tid] = b1[tid];
    __syncthreads();

    float acc[4][4];
    #pragma unroll
    for (int r = 0; r < 4; r++)
        #pragma unroll
        for (int c = 0; c < 4; c++) acc[r][c] = 0.0f;

    for (int k0 = 0; k0 < 128; k0 += 16){
        #pragma unroll
        for (int pp = 0; pp < 8; pp++){
            int idx = tid + pp*256;
            int c = idx & 127, kk = idx >> 7;
            wch[kk][c] = W1[(k0 + kk)*128 + c];
        }
        __syncthreads();
        #pragma unroll
        for (int k = 0; k < 16; k++){
            float a[4], bv[4];
            #pragma unroll
            for (int r = 0; r < 4; r++) a[r] = buf[k0 + k][tr*4 + r];
            #pragma unroll
            for (int c = 0; c < 4; c++) bv[c] = wch[k][tc*4 + c];
            #pragma unroll
            for (int r = 0; r < 4; r++)
                #pragma unroll
                for (int c = 0; c < 4; c++)
                    acc[r][c] = fmaf(a[r], bv[c], acc[r][c]);
        }
        __syncthreads();
    }

    float hval[4][4];
    #pragma unroll
    for (int r = 0; r < 4; r++)
        #pragma unroll
        for (int c = 0; c < 4; c++)
            hval[r][c] = mish_f(acc[r][c] + bias[tc*4 + c]);
    __syncthreads();
    #pragma unroll
    for (int r = 0; r < 4; r++)
        #pragma unroll
        for (int c = 0; c < 4; c++)
            buf[tc*4 + c][tr*4 + r] = hval[r][c];
    if (tid < 128) bias[tid] = b2[tid];

    float acc2[4][4];
    #pragma unroll
    for (int r = 0; r < 4; r++)
        #pragma unroll
        for (int c = 0; c < 4; c++) acc2[r][c] = 0.0f;

    for (int k0 = 0; k0 < 128; k0 += 16){
        #pragma unroll
        for (int pp = 0; pp < 8; pp++){
            int idx = tid + pp*256;
            int c = idx & 127, kk = idx >> 7;
            wch[kk][c] = W2[(k0 + kk)*128 + c];
        }
        __syncthreads();
        #pragma unroll
        for (int k = 0; k < 16; k++){
            float a[4], bv[4];
            #pragma unroll
            for (int r = 0; r < 4; r++) a[r] = buf[k0 + k][tr*4 + r];
            #pragma unroll
            for (int c = 0; c < 4; c++) bv[c] = wch[k][tc*4 + c];
            #pragma unroll
            for (int r = 0; r < 4; r++)
                #pragma unroll
                for (int c = 0; c < 4; c++)
                    acc2[r][c] = fmaf(a[r], bv[c], acc2[r][c]);
        }
        __syncthreads();
    }

    #pragma unroll
    for (int r = 0; r < 4; r++){
        int row = row0 + tr*4 + r;
        float4 x = *(const float4*)&emb[row*128 + tc*4];
        float4 o = make_float4(x.x + acc2[r][0] + bias[tc*4+0],
                               x.y + acc2[r][1] + bias[tc*4+1],
                               x.z + acc2[r][2] + bias[tc*4+2],
                               x.w + acc2[r][3] + bias[tc*4+3]);
        *(float4*)&out[row*128 + tc*4] = o;
    }
}

// prep_kernel: blocks [0,768) = ab, [768,1536) = w2frag. (p0 rides in pair.)
#define PREP_SMEM_BYTES 66560
__global__ __launch_bounds__(256) void prep_kernel(
    const float* __restrict__ emb,
    const float* __restrict__ W1_1, const float* __restrict__ W1_2,
    const float* __restrict__ W1_3,
    const float* __restrict__ W2_1, const float* __restrict__ W2_2,
    const float* __restrict__ W2_3)
{
    extern __shared__ float sh[];
    int bz = blockIdx.x;
    if (bz < 768){
        ab_body(sh, emb, W1_1, W1_2, W1_3, bz & 3, (bz >> 2) & 31, bz >> 7);
    } else {
        w2frag_body(bz - 768, W2_1, W2_2, W2_3);
    }
}

// ---------------------------------------------------------------------------
// pair_mma_kernel: arity-2 via fp16 mma.sync (m16n8k16, f32 acc).
// Block = (pred p, ti). M=64 (j rows), N=256, K=256.
// NO B smem: W2 fragments read directly from L2-hot g_W2h via coalesced
// __ldg LDG.128 inside consume. Pipeline: stage av -> produceA x4 (32KB smem)
// -> 4 back-to-back consumes (256 MMAs/warp, no barriers) -> two-pass
// coalesced epilogue (D staged 32 rows at a time in the dead A region).
// 256 threads, 8 warps (2M x 4N), warp tile 32x64, acc 64 regs.
// __launch_bounds__(256,3): ~36KB smem -> 3 CTAs/SM, 24 warps.
// SMEM bytes: A0..A3 [0,32768) / epilogue D [0,33792) (32x264 floats)
//             av[33792,34816) xi[34816,35328) b2[35328,36352)
// ---------------------------------------------------------------------------
#define PAIR_SMEM_BYTES 36352

#define MMA_F16(d, a, b0v, b1v) \
    asm volatile("mma.sync.aligned.m16n8k16.row.col.f32.f16.f16.f32 " \
        "{%0,%1,%2,%3}, {%4,%5,%6,%7}, {%8,%9}, {%0,%1,%2,%3};" \
        : "+f"(d[0]), "+f"(d[1]), "+f"(d[2]), "+f"(d[3]) \
        : "r"((a).x), "r"((a).y), "r"((a).z), "r"((a).w), \
          "r"(b0v), "r"(b1v))

__global__ __launch_bounds__(256, 3) void pair_mma_kernel(
    const float* __restrict__ emb,
    const float* __restrict__ b1a, const float* __restrict__ b1b, const float* __restrict__ b1c,
    const float* __restrict__ b2a, const float* __restrict__ b2b, const float* __restrict__ b2c,
    const float* __restrict__ W1_0, const float* __restrict__ b1_0,
    const float* __restrict__ W2_0, const float* __restrict__ b2_0,
    float* __restrict__ out)
{
    extern __shared__ char smc[];

    if (blockIdx.x >= 2048){
        if (blockIdx.y == 0)
            p0_body((float*)smc, emb, W1_0, b1_0, W2_0, b2_0, out,
                    blockIdx.x - 2048);
        return;
    }

    float* av   = (float*)(smc + 33792);
    float* xi_s = (float*)(smc + 34816);
    float* b2_s = (float*)(smc + 35328);

    int p = blockIdx.y;
    const float* b1 = (p == 0) ? b1a : (p == 1) ? b1b : b1c;
    const float* b2 = (p == 0) ? b2a : (p == 1) ? b2b : b2c;
    float* outp = out + 262144 + (size_t)p * 33554432;

    int ti = blockIdx.x;              // 0..2047 = b*64 + i
    int b = ti >> 6;
    const float* Pi = g_AB + ((size_t)(p*2) * 2048 + (size_t)ti) * 256;
    const float* Q  = g_AB + ((size_t)(p*2 + 1) * 2048 + (size_t)(b*64)) * 256;

    int t = threadIdx.x;
    int wid = t >> 5, lane = t & 31;
    int wm = wid & 1, wn = wid >> 1;
    int g = lane >> 2, tl = lane & 3;
    int nh = wn >> 1;                 // warp's nhalf
    int npb = (wn & 1) * 4;           // np base within nhalf section
    const uint4* Wn = (const uint4*)g_W2h + (size_t)(p*2 + nh) * 4096;

    // av[k] = P[i][k] + b1[k]; stage xi and full b2
    av[t] = Pi[t] + b1[t];
    if (t < 32){
        float4 v = ((const float4*)(emb + (size_t)ti * 128))[t];
        *(float4*)&xi_s[t*4] = v;
    } else if (t < 96){
        int t2 = t - 32;
        float4 bv = ((const float4*)b2)[t2];
        *(float4*)&b2_s[t2*4] = bv;
    }
    __syncthreads();                  // av/xi/b2 visible

    // A (h) fragments: 2 uint4 per thread per chunk, exact mma layout
    auto produceA = [&](int c, char* Ab){
        #pragma unroll
        for (int e = 0; e < 2; e++){
            int idx = t + e*256;
            int ks = idx >> 7;
            int mt = (idx >> 5) & 3;
            int ln = idx & 31;
            int gg = ln >> 2, tll = ln & 3;
            int j = mt*16 + gg;
            int kb = c*64 + ks*16 + 2*tll;
            const float* qr0 = Q + (size_t)j * 256 + kb;
            const float* qr1 = qr0 + 8 * 256;
            float2 qa0 = *(const float2*)qr0;
            float2 qa1 = *(const float2*)(qr0 + 8);
            float2 qb0 = *(const float2*)qr1;
            float2 qb1 = *(const float2*)(qr1 + 8);
            float2 av0 = *(const float2*)(av + kb);
            float2 av1 = *(const float2*)(av + kb + 8);
            U32 a0 = pack_h2(mish_f(av0.x + qa0.x), mish_f(av0.y + qa0.y));
            U32 a1 = pack_h2(mish_f(av0.x + qb0.x), mish_f(av0.y + qb0.y));
            U32 a2 = pack_h2(mish_f(av1.x + qa1.x), mish_f(av1.y + qa1.y));
            U32 a3 = pack_h2(mish_f(av1.x + qb1.x), mish_f(av1.y + qb1.y));
            *(uint4*)(Ab + (((ks*4 + mt)*32 + ln) << 4)) = make_uint4(a0,a1,a2,a3);
        }
    };

    char* A0 = smc;          char* A1 = smc + 8192;
    char* A2 = smc + 16384;  char* A3 = smc + 24576;

    produceA(0, A0); produceA(1, A1); produceA(2, A2); produceA(3, A3);
    __syncthreads();                  // A visible

    float acc[2][8][4];
    #pragma unroll
    for (int mf = 0; mf < 2; mf++)
        #pragma unroll
        for (int nf = 0; nf < 8; nf++)
            #pragma unroll
            for (int u = 0; u < 4; u++) acc[mf][nf][u] = 0.0f;

    auto consume = [&](char* Ab, int c){
        const uint4* Bg = Wn + c * 1024;
        #pragma unroll
        for (int ks = 0; ks < 4; ks++){
            uint4 aA = *(uint4*)(Ab + (((ks*4 + wm*2    )*32 + lane) << 4));
            uint4 aB = *(uint4*)(Ab + (((ks*4 + wm*2 + 1)*32 + lane) << 4));
            #pragma unroll
            for (int npp = 0; npp < 4; npp++){
                uint4 v = __ldg(Bg + ((ks*8 + npb + npp)*32 + lane));
                MMA_F16(acc[0][2*npp    ], aA, v.x, v.y);
                MMA_F16(acc[1][2*npp    ], aB, v.x, v.y);
                MMA_F16(acc[0][2*npp + 1], aA, v.z, v.w);
                MMA_F16(acc[1][2*npp + 1], aB, v.z, v.w);
            }
        }
    };

    consume(A0, 0);
    consume(A1, 1);
    consume(A2, 2);
    consume(A3, 3);

    // ---- epilogue: two 32-row passes through smem, coalesced writeback ----
    float* D = (float*)smc;           // [32][264] floats = 33792 B
    size_t rowbase = (size_t)ti * 64;
    const float* embB = emb + (size_t)(b*64) * 128;

    #pragma unroll
    for (int pass = 0; pass < 2; pass++){
        __syncthreads();              // A (or prev D) region free
        if (wm == pass){
            #pragma unroll
            for (int mf = 0; mf < 2; mf++){
                int jr0 = mf*16 + g;
                int jr1 = jr0 + 8;
                #pragma unroll
                for (int npp = 0; npp < 4; npp++){
                    #pragma unroll
                    for (int inner = 0; inner < 2; inner++){
                        int nf = 2*npp + inner;
                        int col = nh*128 + (npb + npp)*16 + inner*8 + 2*tl;
                        *(float2*)&D[jr0*264 + col] =
                            make_float2(acc[mf][nf][0], acc[mf][nf][1]);
                        *(float2*)&D[jr1*264 + col] =
                            make_float2(acc[mf][nf][2], acc[mf][nf][3]);
                    }
                }
            }
        }
        __syncthreads();
        int rb = pass * 32;
        #pragma unroll
        for (int it = 0; it < 8; it++){
            int idx = t + it*256;
            int r = idx >> 6, c4 = idx & 63;
            int col = c4 * 4;
            float4 d = *(float4*)&D[r*264 + col];
            float4 xv;
            if (col < 128) xv = *(float4*)&xi_s[col];
            else xv = __ldg((const float4*)(embB + (size_t)(rb + r)*128 + (col - 128)));
            float4 bb = *(float4*)&b2_s[col];
            float4 o = make_float4(d.x + xv.x + bb.x, d.y + xv.y + bb.y,
                                   d.z + xv.z + bb.z, d.w + xv.w + bb.w);
            *(float4*)&outp[(rowbase + rb + r)*256 + col] = o;
        }
    }
}

// ---------------------------------------------------------------------------
extern "C" void kernel_launch(void* const* d_in, const int* in_sizes, int n_in,
                              void* d_out, int out_size)
{
    (void)in_sizes; (void)n_in; (void)out_size;
    const float* emb  = (const float*)d_in[0];
    const float* W1_0 = (const float*)d_in[2];
    const float* b1_0 = (const float*)d_in[3];
    const float* W2_0 = (const float*)d_in[4];
    const float* b2_0 = (const float*)d_in[5];
    const float* W1_1 = (const float*)d_in[6];
    const float* b1_1 = (const float*)d_in[7];
    const float* W2_1 = (const float*)d_in[8];
    const float* b2_1 = (const float*)d_in[9];
    const float* W1_2 = (const float*)d_in[10];
    const float* b1_2 = (const float*)d_in[11];
    const float* W2_2 = (const float*)d_in[12];
    const float* b2_2 = (const float*)d_in[13];
    const float* W1_3 = (const float*)d_in[14];
    const float* b1_3 = (const float*)d_in[15];
    const float* W2_3 = (const float*)d_in[16];
    const float* b2_3 = (const float*)d_in[17];
    float* out = (float*)d_out;

    static int smem_set = 0;
    if (!smem_set){
        cudaFuncSetAttribute(pair_mma_kernel,
                             cudaFuncAttributeMaxDynamicSharedMemorySize,
                             PAIR_SMEM_BYTES);
        cudaFuncSetAttribute(prep_kernel,
                             cudaFuncAttributeMaxDynamicSharedMemorySize,
                             PREP_SMEM_BYTES);
        smem_set = 1;
    }

    prep_kernel<<<1536, 256, PREP_SMEM_BYTES>>>(
        emb,
        W1_1, W1_2, W1_3,
        W2_1, W2_2, W2_3);
    pair_mma_kernel<<<dim3(2112, 3), 256, PAIR_SMEM_BYTES>>>(
        emb,
        b1_1, b1_2, b1_3,
        b2_1, b2_2, b2_3,
        W1_0, b1_0, W2_0, b2_0,
        out);
}

// round 17
// speedup vs baseline: 1.0201x; 1.0201x over previous
#include <cuda_runtime.h>

typedef unsigned int U32;
typedef unsigned short U16;

static __device__ __forceinline__ float mish_f(float x){
    float e  = __expf(fminf(x, 30.0f));
    float u  = 1.0f + e;
    float u2 = u * u;
    float d  = u2 + 1.0f;
    float r  = __int_as_float(0x7EF311C2 - __float_as_int(d));
    r = r * (2.0f - d * r);
    r = r * (2.0f - d * r);
    return x * (u2 - 1.0f) * r;
}

// g_AB: [pred(3)][half(2)][row(2048)][col(256)]  (P = x@W1_top, Q = x@W1_bot)
__device__ float g_AB[6 * 2048 * 256];
// g_W2h: W2 in fp16, fragment order: [pred(3)][nhalf(2)][chunk64(4)][8192 halves]
__device__ U16 g_W2h[3 * 65536];

static __device__ __forceinline__ U32 pack_h2(float lo, float hi){
    U32 r;
    asm("cvt.rn.f16x2.f32 %0, %1, %2;" : "=r"(r) : "f"(hi), "f"(lo));
    return r;
}

static __device__ __forceinline__ void cp16(U32 dst, const void* src){
    asm volatile("cp.async.cg.shared.global [%0], [%1], 16;"
                 :: "r"(dst), "l"(src) : "memory");
}

// ---------------------------------------------------------------------------
// prep bodies
// ---------------------------------------------------------------------------
static __device__ void w2frag_body(int blk,
    const float* __restrict__ W2a, const float* __restrict__ W2b,
    const float* __restrict__ W2c)
{
    int idx = blk * 256 + threadIdx.x;
    int p = idx >> 16;
    int rem = idx & 65535;
    int k = rem >> 8, n = rem & 255;
    const float* W2 = (p == 0) ? W2a : (p == 1) ? W2b : W2c;
    float v = W2[k * 256 + n];
    U16 hv;
    asm("{ .reg .f16 t; cvt.rn.f16.f32 t, %1; mov.b16 %0, t; }" : "=h"(hv) : "f"(v));
    int c = k >> 6, kk = k & 63;
    int ks = kk >> 4, r = kk & 15;
    int hi = r >> 3, r8 = r & 7, tl = r8 >> 1, comp = r8 & 1;
    int nhalf = n >> 7, nl = n & 127;
    int nt = nl >> 3, np = nt >> 1, odd = nt & 1, g = nl & 7;
    int lane = g * 4 + tl;
    int halfidx = ((ks * 8 + np) * 32 + lane) * 8 + (odd * 2 + hi) * 2 + comp;
    g_W2h[((p * 2 + nhalf) * 4 + c) * 8192 + halfidx] = hv;
}

static __device__ void ab_body(float* sh,
    const float* __restrict__ emb,
    const float* __restrict__ W1a, const float* __restrict__ W1b,
    const float* __restrict__ W1c,
    int bx, int by, int z)
{
    float (*Xs)[65] = (float(*)[65])sh;
    float (*Ws)[64] = (float(*)[64])(sh + 128*65);
    int p = z >> 1, half = z & 1;
    const float* W = (p == 0 ? W1a : (p == 1 ? W1b : W1c)) + half * 128 * 256;
    int row0 = by * 64;
    int col0 = bx * 64;
    int tid = threadIdx.x;
    int tr = tid >> 4, tc = tid & 15;

    #pragma unroll
    for (int it = 0; it < 32; it++){
        int idx = tid + it*256;
        int r = idx >> 7, k = idx & 127;
        Xs[k][r] = emb[(row0 + r)*128 + k];
    }
    #pragma unroll
    for (int it = 0; it < 32; it++){
        int idx = tid + it*256;
        int k = idx >> 6, c = idx & 63;
        Ws[k][c] = W[k*256 + col0 + c];
    }
    __syncthreads();

    float acc[4][4];
    #pragma unroll
    for (int r = 0; r < 4; r++)
        #pragma unroll
        for (int c = 0; c < 4; c++) acc[r][c] = 0.0f;

    #pragma unroll 4
    for (int k = 0; k < 128; k++){
        float a[4], bv[4];
        #pragma unroll
        for (int r = 0; r < 4; r++) a[r] = Xs[k][tr*4 + r];
        #pragma unroll
        for (int c = 0; c < 4; c++) bv[c] = Ws[k][tc*4 + c];
        #pragma unroll
        for (int r = 0; r < 4; r++)
            #pragma unroll
            for (int c = 0; c < 4; c++)
                acc[r][c] = fmaf(a[r], bv[c], acc[r][c]);
    }

    float* out = g_AB + (size_t)z * 2048 * 256;
    #pragma unroll
    for (int r = 0; r < 4; r++){
        float4 v = make_float4(acc[r][0], acc[r][1], acc[r][2], acc[r][3]);
        *(float4*)&out[(row0 + tr*4 + r)*256 + col0 + tc*4] = v;
    }
}

static __device__ void p0_body(float* sh,
    const float* __restrict__ emb,
    const float* __restrict__ W1, const float* __restrict__ b1,
    const float* __restrict__ W2, const float* __restrict__ b2,
    float* __restrict__ out, int blk)
{
    float (*buf)[33] = (float(*)[33])sh;
    float (*wch)[128] = (float(*)[128])(sh + 4224);
    float* bias = sh + 4224 + 2048;
    int row0 = blk * 32;
    int tid = threadIdx.x;
    int tr = tid >> 5, tc = tid & 31;

    for (int idx = tid; idx < 32*128; idx += 256){
        int k = idx & 127, r = idx >> 7;
        buf[k][r] = emb[(row0 + r)*128 + k];
    }
    if (tid < 128) bias[tid] = b1[tid];
    __syncthreads();

    float acc[4][4];
    #pragma unroll
    for (int r = 0; r < 4; r++)
        #pragma unroll
        for (int c = 0; c < 4; c++) acc[r][c] = 0.0f;

    for (int k0 = 0; k0 < 128; k0 += 16){
        #pragma unroll
        for (int pp = 0; pp < 8; pp++){
            int idx = tid + pp*256;
            int c = idx & 127, kk = idx >> 7;
            wch[kk][c] = W1[(k0 + kk)*128 + c];
        }
        __syncthreads();
        #pragma unroll
        for (int k = 0; k < 16; k++){
            float a[4], bv[4];
            #pragma unroll
            for (int r = 0; r < 4; r++) a[r] = buf[k0 + k][tr*4 + r];
            #pragma unroll
            for (int c = 0; c < 4; c++) bv[c] = wch[k][tc*4 + c];
            #pragma unroll
            for (int r = 0; r < 4; r++)
                #pragma unroll
                for (int c = 0; c < 4; c++)
                    acc[r][c] = fmaf(a[r], bv[c], acc[r][c]);
        }
        __syncthreads();
    }

    float hval[4][4];
    #pragma unroll
    for (int r = 0; r < 4; r++)
        #pragma unroll
        for (int c = 0; c < 4; c++)
            hval[r][c] = mish_f(acc[r][c] + bias[tc*4 + c]);
    __syncthreads();
    #pragma unroll
    for (int r = 0; r < 4; r++)
        #pragma unroll
        for (int c = 0; c < 4; c++)
            buf[tc*4 + c][tr*4 + r] = hval[r][c];
    if (tid < 128) bias[tid] = b2[tid];

    float acc2[4][4];
    #pragma unroll
    for (int r = 0; r < 4; r++)
        #pragma unroll
        for (int c = 0; c < 4; c++) acc2[r][c] = 0.0f;

    for (int k0 = 0; k0 < 128; k0 += 16){
        #pragma unroll
        for (int pp = 0; pp < 8; pp++){
            int idx = tid + pp*256;
            int c = idx & 127, kk = idx >> 7;
            wch[kk][c] = W2[(k0 + kk)*128 + c];
        }
        __syncthreads();
        #pragma unroll
        for (int k = 0; k < 16; k++){
            float a[4], bv[4];
            #pragma unroll
            for (int r = 0; r < 4; r++) a[r] = buf[k0 + k][tr*4 + r];
            #pragma unroll
            for (int c = 0; c < 4; c++) bv[c] = wch[k][tc*4 + c];
            #pragma unroll
            for (int r = 0; r < 4; r++)
                #pragma unroll
                for (int c = 0; c < 4; c++)
                    acc2[r][c] = fmaf(a[r], bv[c], acc2[r][c]);
        }
        __syncthreads();
    }

    #pragma unroll
    for (int r = 0; r < 4; r++){
        int row = row0 + tr*4 + r;
        float4 x = *(const float4*)&emb[row*128 + tc*4];
        float4 o = make_float4(x.x + acc2[r][0] + bias[tc*4+0],
                               x.y + acc2[r][1] + bias[tc*4+1],
                               x.z + acc2[r][2] + bias[tc*4+2],
                               x.w + acc2[r][3] + bias[tc*4+3]);
        *(float4*)&out[row*128 + tc*4] = o;
    }
}

// prep_kernel: blocks [0,768) = ab, [768,1536) = w2frag. (p0 rides in pair.)
#define PREP_SMEM_BYTES 66560
__global__ __launch_bounds__(256) void prep_kernel(
    const float* __restrict__ emb,
    const float* __restrict__ W1_1, const float* __restrict__ W1_2,
    const float* __restrict__ W1_3,
    const float* __restrict__ W2_1, const float* __restrict__ W2_2,
    const float* __restrict__ W2_3)
{
    extern __shared__ float sh[];
    int bz = blockIdx.x;
    if (bz < 768){
        ab_body(sh, emb, W1_1, W1_2, W1_3, bz & 3, (bz >> 2) & 31, bz >> 7);
    } else {
        w2frag_body(bz - 768, W2_1, W2_2, W2_3);
    }
}

// ---------------------------------------------------------------------------
// pair_mma_kernel: arity-2 via fp16 mma.sync (m16n8k16, f32 acc).
// Block = (pred p, ti). M=64, N=256, K=256 in EIGHT chunks of 32 (so smem
// fits 3 CTAs/SM): A = 8 x 4KB produced up front; B = 2 x 16KB double
// buffer, cp.async from L2-hot g_W2h with overlapped refills (R16 showed
// direct-LDG B goes to DRAM — staging via cp.async is mandatory).
// Ascending chunk order == R15 accumulation order (bit-identical).
// 256 threads, 8 warps (2M x 4N), warp tile 32x64, acc 64 regs.
// __launch_bounds__(256,3): 68.1KB smem -> 3 CTAs/SM, 24 warps.
// SMEM bytes: A[0,32768) B0[32768,49152) B1[49152,65536)
//             av[65536,66560) xi[66560,67072) b2[67072,68096)
// Epilogue D tile: [32][264] floats at offset 0 (33792 B, dead A+B0 head).
// ---------------------------------------------------------------------------
#define PAIR_SMEM_BYTES 68096

#define MMA_F16(d, a, b0v, b1v) \
    asm volatile("mma.sync.aligned.m16n8k16.row.col.f32.f16.f16.f32 " \
        "{%0,%1,%2,%3}, {%4,%5,%6,%7}, {%8,%9}, {%0,%1,%2,%3};" \
        : "+f"(d[0]), "+f"(d[1]), "+f"(d[2]), "+f"(d[3]) \
        : "r"((a).x), "r"((a).y), "r"((a).z), "r"((a).w), \
          "r"(b0v), "r"(b1v))

__global__ __launch_bounds__(256, 3) void pair_mma_kernel(
    const float* __restrict__ emb,
    const float* __restrict__ b1a, const float* __restrict__ b1b, const float* __restrict__ b1c,
    const float* __restrict__ b2a, const float* __restrict__ b2b, const float* __restrict__ b2c,
    const float* __restrict__ W1_0, const float* __restrict__ b1_0,
    const float* __restrict__ W2_0, const float* __restrict__ b2_0,
    float* __restrict__ out)
{
    extern __shared__ char smc[];

    if (blockIdx.x >= 2048){
        if (blockIdx.y == 0)
            p0_body((float*)smc, emb, W1_0, b1_0, W2_0, b2_0, out,
                    blockIdx.x - 2048);
        return;
    }

    float* av   = (float*)(smc + 65536);
    float* xi_s = (float*)(smc + 66560);
    float* b2_s = (float*)(smc + 67072);
    U32 smem32;
    asm("{ .reg .u64 t; cvta.to.shared.u64 t, %1; cvt.u32.u64 %0, t; }"
        : "=r"(smem32) : "l"(smc));

    int p = blockIdx.y;
    const float* b1 = (p == 0) ? b1a : (p == 1) ? b1b : b1c;
    const float* b2 = (p == 0) ? b2a : (p == 1) ? b2b : b2c;
    float* outp = out + 262144 + (size_t)p * 33554432;

    int ti = blockIdx.x;
    int b = ti >> 6;
    const float* Pi = g_AB + ((size_t)(p*2) * 2048 + (size_t)ti) * 256;
    const float* Q  = g_AB + ((size_t)(p*2 + 1) * 2048 + (size_t)(b*64)) * 256;
    const uint4* W0 = (const uint4*)g_W2h + (size_t)(p*2    ) * 4096;
    const uint4* W1 = (const uint4*)g_W2h + (size_t)(p*2 + 1) * 4096;

    int t = threadIdx.x;
    int wid = t >> 5, lane = t & 31;
    int wm = wid & 1, wn = wid >> 1;
    int g = lane >> 2, tl = lane & 3;
    int nh = wn >> 1;
    int npb = (wn & 1) * 4;

    // av[k] = P[i][k] + b1[k]; stage xi and full b2
    av[t] = Pi[t] + b1[t];
    if (t < 32){
        float4 v = ((const float4*)(emb + (size_t)ti * 128))[t];
        *(float4*)&xi_s[t*4] = v;
    } else if (t < 96){
        int t2 = t - 32;
        float4 bv = ((const float4*)b2)[t2];
        *(float4*)&b2_s[t2*4] = bv;
    }

    // B chunk (K=32) async copy: both nh sections, 16KB = 1024 uint4.
    // smem layout: [nh(2)][ks2(2)][np(8)][lane(32)] uint4.
    auto produceW = [&](int c, U32 Bs32){
        int c64 = c >> 1, half = (c & 1) * 512;
        #pragma unroll
        for (int it = 0; it < 4; it++){
            int idx = t + it*256;               // 0..1023; it<2 -> nh0
            const uint4* base = (it < 2) ? W0 : W1;
            int rest = idx & 511;
            cp16(Bs32 + (U32)idx * 16u, base + c64*1024 + half + rest);
        }
        asm volatile("cp.async.commit_group;" ::: "memory");
    };

    // A (h) fragments for K=32 chunk: 1 uint4 per thread, exact mma layout.
    auto produceA = [&](int c, char* Ab){
        int ks2 = t >> 7;
        int mt = (t >> 5) & 3;
        int ln = t & 31;
        int gg = ln >> 2, tll = ln & 3;
        int j = mt*16 + gg;
        int kb = c*32 + ks2*16 + 2*tll;
        const float* qr0 = Q + (size_t)j * 256 + kb;
        const float* qr1 = qr0 + 8 * 256;
        float2 qa0 = *(const float2*)qr0;
        float2 qa1 = *(const float2*)(qr0 + 8);
        float2 qb0 = *(const float2*)qr1;
        float2 qb1 = *(const float2*)(qr1 + 8);
        float2 av0 = *(const float2*)(av + kb);
        float2 av1 = *(const float2*)(av + kb + 8);
        U32 a0 = pack_h2(mish_f(av0.x + qa0.x), mish_f(av0.y + qa0.y));
        U32 a1 = pack_h2(mish_f(av0.x + qb0.x), mish_f(av0.y + qb0.y));
        U32 a2 = pack_h2(mish_f(av1.x + qa1.x), mish_f(av1.y + qa1.y));
        U32 a3 = pack_h2(mish_f(av1.x + qb1.x), mish_f(av1.y + qb1.y));
        *(uint4*)(Ab + (((ks2*4 + mt)*32 + ln) << 4)) = make_uint4(a0,a1,a2,a3);
    };

    float acc[2][8][4];
    #pragma unroll
    for (int mf = 0; mf < 2; mf++)
        #pragma unroll
        for (int nf = 0; nf < 8; nf++)
            #pragma unroll
            for (int u = 0; u < 4; u++) acc[mf][nf][u] = 0.0f;

    auto consume = [&](char* Ab, char* Bb){
        char* Bn = Bb + nh * 8192;
        #pragma unroll
        for (int ks2 = 0; ks2 < 2; ks2++){
            uint4 aA = *(uint4*)(Ab + (((ks2*4 + wm*2    )*32 + lane) << 4));
            uint4 aB = *(uint4*)(Ab + (((ks2*4 + wm*2 + 1)*32 + lane) << 4));
            #pragma unroll
            for (int npp = 0; npp < 4; npp++){
                uint4 v = *(uint4*)(Bn + (((ks2*8 + npb + npp)*32 + lane) << 4));
                MMA_F16(acc[0][2*npp    ], aA, v.x, v.y);
                MMA_F16(acc[1][2*npp    ], aB, v.x, v.y);
                MMA_F16(acc[0][2*npp + 1], aA, v.z, v.w);
                MMA_F16(acc[1][2*npp + 1], aB, v.z, v.w);
            }
        }
    };

    char* A  = smc;                          // chunk c at A + c*4096
    char* B0s = smc + 32768;  char* B1s = smc + 49152;
    U32 B0a = smem32 + 32768, B1a = smem32 + 49152;

    produceW(0, B0a);
    produceW(1, B1a);
    __syncthreads();                  // av/xi/b2 visible
    #pragma unroll
    for (int c = 0; c < 8; c++) produceA(c, A + c*4096);
    asm volatile("cp.async.wait_group 0;" ::: "memory");
    __syncthreads();                  // A + B{0,1} visible

    consume(A        , B0s);
    __syncthreads();
    produceW(2, B0a);
    consume(A + 4096 , B1s);
    asm volatile("cp.async.wait_group 0;" ::: "memory");
    __syncthreads();
    produceW(3, B1a);
    consume(A + 8192 , B0s);
    asm volatile("cp.async.wait_group 0;" ::: "memory");
    __syncthreads();
    produceW(4, B0a);
    consume(A + 12288, B1s);
    asm volatile("cp.async.wait_group 0;" ::: "memory");
    __syncthreads();
    produceW(5, B1a);
    consume(A + 16384, B0s);
    asm volatile("cp.async.wait_group 0;" ::: "memory");
    __syncthreads();
    produceW(6, B0a);
    consume(A + 20480, B1s);
    asm volatile("cp.async.wait_group 0;" ::: "memory");
    __syncthreads();
    produceW(7, B1a);
    consume(A + 24576, B0s);
    asm volatile("cp.async.wait_group 0;" ::: "memory");
    __syncthreads();
    consume(A + 28672, B1s);

    // ---- epilogue: two 32-row passes through smem, coalesced writeback ----
    float* D = (float*)smc;           // [32][264] floats = 33792 B
    size_t rowbase = (size_t)ti * 64;
    const float* embB = emb + (size_t)(b*64) * 128;

    #pragma unroll
    for (int pass = 0; pass < 2; pass++){
        __syncthreads();
        if (wm == pass){
            #pragma unroll
            for (int mf = 0; mf < 2; mf++){
                int jr0 = mf*16 + g;
                int jr1 = jr0 + 8;
                #pragma unroll
                for (int npp = 0; npp < 4; npp++){
                    #pragma unroll
                    for (int inner = 0; inner < 2; inner++){
                        int nf = 2*npp + inner;
                        int col = nh*128 + (npb + npp)*16 + inner*8 + 2*tl;
                        *(float2*)&D[jr0*264 + col] =
                            make_float2(acc[mf][nf][0], acc[mf][nf][1]);
                        *(float2*)&D[jr1*264 + col] =
                            make_float2(acc[mf][nf][2], acc[mf][nf][3]);
                    }
                }
            }
        }
        __syncthreads();
        int rb = pass * 32;
        #pragma unroll
        for (int it = 0; it < 8; it++){
            int idx = t + it*256;
            int r = idx >> 6, c4 = idx & 63;
            int col = c4 * 4;
            float4 d = *(float4*)&D[r*264 + col];
            float4 xv;
            if (col < 128) xv = *(float4*)&xi_s[col];
            else xv = __ldg((const float4*)(embB + (size_t)(rb + r)*128 + (col - 128)));
            float4 bb = *(float4*)&b2_s[col];
            float4 o = make_float4(d.x + xv.x + bb.x, d.y + xv.y + bb.y,
                                   d.z + xv.z + bb.z, d.w + xv.w + bb.w);
            *(float4*)&outp[(rowbase + rb + r)*256 + col] = o;
        }
    }
}

// ---------------------------------------------------------------------------
extern "C" void kernel_launch(void* const* d_in, const int* in_sizes, int n_in,
                              void* d_out, int out_size)
{
    (void)in_sizes; (void)n_in; (void)out_size;
    const float* emb  = (const float*)d_in[0];
    const float* W1_0 = (const float*)d_in[2];
    const float* b1_0 = (const float*)d_in[3];
    const float* W2_0 = (const float*)d_in[4];
    const float* b2_0 = (const float*)d_in[5];
    const float* W1_1 = (const float*)d_in[6];
    const float* b1_1 = (const float*)d_in[7];
    const float* W2_1 = (const float*)d_in[8];
    const float* b2_1 = (const float*)d_in[9];
    const float* W1_2 = (const float*)d_in[10];
    const float* b1_2 = (const float*)d_in[11];
    const float* W2_2 = (const float*)d_in[12];
    const float* b2_2 = (const float*)d_in[13];
    const float* W1_3 = (const float*)d_in[14];
    const float* b1_3 = (const float*)d_in[15];
    const float* W2_3 = (const float*)d_in[16];
    const float* b2_3 = (const float*)d_in[17];
    float* out = (float*)d_out;

    static int smem_set = 0;
    if (!smem_set){
        cudaFuncSetAttribute(pair_mma_kernel,
                             cudaFuncAttributeMaxDynamicSharedMemorySize,
                             PAIR_SMEM_BYTES);
        cudaFuncSetAttribute(prep_kernel,
                             cudaFuncAttributeMaxDynamicSharedMemorySize,
                             PREP_SMEM_BYTES);
        smem_set = 1;
    }

    prep_kernel<<<1536, 256, PREP_SMEM_BYTES>>>(
        emb,
        W1_1, W1_2, W1_3,
        W2_1, W2_2, W2_3);
    pair_mma_kernel<<<dim3(2112, 3), 256, PAIR_SMEM_BYTES>>>(
        emb,
        b1_1, b1_2, b1_3,
        b2_1, b2_2, b2_3,
        W1_0, b1_0, W2_0, b2_0,
        out);
}